// round 5
// baseline (speedup 1.0000x reference)
#include <cuda_runtime.h>

typedef unsigned long long ull_t;

// ---------------- scratch (device globals: allocation-free rule) -------------
__device__ float g_qkv[(size_t)4096 * 64 * 288];   // [win][tok][3*C]  (302 MB)
__device__ float g_x2 [(size_t)64 * 4096 * 96];    // x + attn branch  (100 MB)

// ---------------- packed f32x2 helpers (FFMA2 path, 2x fp32 rate) ------------
static __device__ __forceinline__ ull_t pk2(float lo, float hi) {
    ull_t d;
    asm("mov.b64 %0, {%1,%2};" : "=l"(d)
        : "r"(__float_as_uint(lo)), "r"(__float_as_uint(hi)));
    return d;
}
static __device__ __forceinline__ void up2(ull_t v, float& lo, float& hi) {
    unsigned a, b;
    asm("mov.b64 {%0,%1}, %2;" : "=r"(a), "=r"(b) : "l"(v));
    lo = __uint_as_float(a); hi = __uint_as_float(b);
}
static __device__ __forceinline__ void fma2(ull_t& acc, ull_t a, ull_t b) {
    asm("fma.rn.f32x2 %0, %1, %2, %0;" : "+l"(acc) : "l"(a), "l"(b));
}

// =============================================================================
// K1: LayerNorm1 + shift(-4,-4) + window partition + QKV GEMM
// grid 4096 (one window), 256 threads. smem: xst[96][66] + ws[288][33] = 62 KB
// =============================================================================
__global__ void __launch_bounds__(256, 1) k1_ln_qkv(
    const float* __restrict__ x, const float* __restrict__ g1,
    const float* __restrict__ b1, const float* __restrict__ qw,
    const float* __restrict__ qb)
{
    extern __shared__ float sm[];
    float* xst = sm;            // [96][66]  normalized activations, transposed
    float* ws  = sm + 96 * 66;  // [288][33] weight k-chunk (padded)

    const int wnd = blockIdx.x;
    const int b = wnd >> 6, wy = (wnd >> 3) & 7, wx = wnd & 7;
    const int tid = threadIdx.x, lane = tid & 31, warp = tid >> 5;

    {   // ---- LN + gather (4 lanes per token, 24 ch each) ----
        int t = (warp << 3) + (lane >> 2);
        int part = lane & 3;
        int ty = t >> 3, tx = t & 7;
        int y0 = ((wy << 3) + ty + 4) & 63;      // roll(-4): src = (pos+4) mod 64
        int x0 = ((wx << 3) + tx + 4) & 63;
        const float4* src = reinterpret_cast<const float4*>(
            x + ((size_t)((b << 12) + (y0 << 6) + x0)) * 96 + part * 24);
        float v[24]; float s = 0.f, s2 = 0.f;
        #pragma unroll
        for (int i = 0; i < 6; i++) {
            float4 f = src[i];
            v[4*i] = f.x; v[4*i+1] = f.y; v[4*i+2] = f.z; v[4*i+3] = f.w;
        }
        #pragma unroll
        for (int i = 0; i < 24; i++) { s += v[i]; s2 += v[i] * v[i]; }
        s  += __shfl_xor_sync(0xffffffffu, s, 1);  s  += __shfl_xor_sync(0xffffffffu, s, 2);
        s2 += __shfl_xor_sync(0xffffffffu, s2, 1); s2 += __shfl_xor_sync(0xffffffffu, s2, 2);
        float mu   = s * (1.f / 96.f);
        float rstd = rsqrtf(s2 * (1.f / 96.f) - mu * mu + 1e-5f);
        #pragma unroll
        for (int i = 0; i < 24; i++) {
            int c = part * 24 + i;
            xst[c * 66 + t] = (v[i] - mu) * rstd * g1[c] + b1[c];
        }
    }

    // ---- QKV GEMM: out[64][288]; thread tile = 8 tokens (as 4 pairs) x 9 outs
    const int tt = warp, oo = lane;
    ull_t acc[4][9];
    #pragma unroll
    for (int u = 0; u < 4; u++)
        #pragma unroll
        for (int p = 0; p < 9; p++) acc[u][p] = 0ull;

    for (int kb = 0; kb < 96; kb += 32) {
        __syncthreads();
        #pragma unroll
        for (int r = 0; r < 36; r++) {              // 288*32 / 256
            int idx = tid + r * 256;
            int o = idx >> 5, c = idx & 31;
            ws[o * 33 + c] = qw[o * 96 + kb + c];
        }
        __syncthreads();
        #pragma unroll
        for (int c = 0; c < 32; c++) {
            const ull_t* ar = reinterpret_cast<const ull_t*>(
                xst + (kb + c) * 66 + (tt << 3));   // broadcast LDS.64
            ull_t a0 = ar[0], a1 = ar[1], a2 = ar[2], a3 = ar[3];
            #pragma unroll
            for (int p = 0; p < 9; p++) {
                float wv = ws[(oo * 9 + p) * 33 + c];
                ull_t w2 = pk2(wv, wv);
                fma2(acc[0][p], a0, w2); fma2(acc[1][p], a1, w2);
                fma2(acc[2][p], a2, w2); fma2(acc[3][p], a3, w2);
            }
        }
    }

    float* dst = g_qkv + (size_t)wnd * 64 * 288;
    #pragma unroll
    for (int p = 0; p < 9; p++) {
        int o = oo * 9 + p;
        float bb = qb[o];
        float sc = (o < 96) ? 0.20412414523193154f : 1.f;   // q *= 24^-0.5
        #pragma unroll
        for (int u = 0; u < 4; u++) {
            float lo, hi; up2(acc[u][p], lo, hi);
            int t0 = (tt << 3) + 2 * u;
            dst[(size_t)t0 * 288 + o]       = (lo + bb) * sc;
            dst[(size_t)(t0 + 1) * 288 + o] = (hi + bb) * sc;
        }
    }
}

// =============================================================================
// K2: windowed attention (bias + shift mask + softmax) + proj + reverse/unshift
//     + residual  ->  g_x2
// grid 4096, 256 threads (thread = (head, row)). smem 109 KB
// =============================================================================
__global__ void __launch_bounds__(256, 1) k2_attn_proj(
    const float* __restrict__ x, const float* __restrict__ btab,
    const float* __restrict__ pw, const float* __restrict__ pb)
{
    extern __shared__ float sm[];
    float* ksm = sm;                     // [4][64][24]
    float* vsm = sm + 6144;              // [4][64][24]
    float* aot = sm + 12288;             // [96][66] attn out, transposed
    float* pws = sm + 12288 + 6336;      // [96][97] proj weights (padded)

    const int wnd = blockIdx.x;
    const int b = wnd >> 6, wy = (wnd >> 3) & 7, wx = wnd & 7;
    const int tid = threadIdx.x;
    const float* qkvbase = g_qkv + (size_t)wnd * 64 * 288;
    const int h = tid >> 6, i = tid & 63;

    {   // ---- stage K, V rows ----
        const float4* sk = reinterpret_cast<const float4*>(qkvbase + i * 288 +  96 + h * 24);
        const float4* sv = reinterpret_cast<const float4*>(qkvbase + i * 288 + 192 + h * 24);
        float4* dk = reinterpret_cast<float4*>(ksm + (h * 64 + i) * 24);
        float4* dv = reinterpret_cast<float4*>(vsm + (h * 64 + i) * 24);
        #pragma unroll
        for (int u = 0; u < 6; u++) { dk[u] = sk[u]; dv[u] = sv[u]; }
    }
    for (int idx = tid; idx < 96 * 96; idx += 256) {  // stage proj_w
        int o = idx / 96, c = idx - o * 96;
        pws[o * 97 + c] = pw[idx];
    }

    ull_t q2[12];
    {   // own q row in registers (already scaled in K1)
        const float4* sq = reinterpret_cast<const float4*>(qkvbase + i * 288 + h * 24);
        #pragma unroll
        for (int u = 0; u < 6; u++) {
            float4 f = sq[u];
            q2[2*u]   = pk2(f.x, f.y);
            q2[2*u+1] = pk2(f.z, f.w);
        }
    }
    __syncthreads();

    const int iy = i >> 3, ix = i & 7;
    const int cnti = ((wy == 7) ? ((iy < 4) ? 1 : 2) : 0) * 3
                   + ((wx == 7) ? ((ix < 4) ? 1 : 2) : 0);

    float s[64];
    const float* kb_ = ksm + h * 64 * 24;
    #pragma unroll
    for (int j = 0; j < 64; j++) {
        const ull_t* kr = reinterpret_cast<const ull_t*>(kb_ + j * 24);
        ull_t a = 0ull;
        #pragma unroll
        for (int u = 0; u < 12; u++) fma2(a, q2[u], kr[u]);
        float lo, hi; up2(a, lo, hi);
        int jy = j >> 3, jx = j & 7;
        float bias = btab[((iy - jy + 7) * 15 + (ix - jx + 7)) * 4 + h];
        int cntj = ((wy == 7) ? ((jy < 4) ? 1 : 2) : 0) * 3
                 + ((wx == 7) ? ((jx < 4) ? 1 : 2) : 0);
        s[j] = lo + hi + bias + ((cnti != cntj) ? -100.f : 0.f);
    }
    float mx = -1e30f;
    #pragma unroll
    for (int j = 0; j < 64; j++) mx = fmaxf(mx, s[j]);
    float sum = 0.f;
    #pragma unroll
    for (int j = 0; j < 64; j++) { float e = __expf(s[j] - mx); s[j] = e; sum += e; }
    float inv = 1.f / sum;

    ull_t o2[12];
    #pragma unroll
    for (int u = 0; u < 12; u++) o2[u] = 0ull;
    const float* vb_ = vsm + h * 64 * 24;
    #pragma unroll
    for (int j = 0; j < 64; j++) {
        ull_t p2 = pk2(s[j], s[j]);
        const ull_t* vr = reinterpret_cast<const ull_t*>(vb_ + j * 24);
        #pragma unroll
        for (int u = 0; u < 12; u++) fma2(o2[u], p2, vr[u]);
    }
    #pragma unroll
    for (int u = 0; u < 12; u++) {
        float lo, hi; up2(o2[u], lo, hi);
        aot[(h * 24 + 2 * u)     * 66 + i] = lo * inv;
        aot[(h * 24 + 2 * u + 1) * 66 + i] = hi * inv;
    }
    __syncthreads();

    // ---- proj: out[64][96]; thread tile = 8 tokens x 3 outs ----
    const int tt = tid >> 5, oo = tid & 31;
    ull_t pa[4][3];
    #pragma unroll
    for (int u = 0; u < 4; u++)
        #pragma unroll
        for (int p = 0; p < 3; p++) pa[u][p] = 0ull;

    #pragma unroll 4
    for (int k = 0; k < 96; k++) {
        const ull_t* ar = reinterpret_cast<const ull_t*>(aot + k * 66 + (tt << 3));
        ull_t a0 = ar[0], a1 = ar[1], a2 = ar[2], a3 = ar[3];
        #pragma unroll
        for (int p = 0; p < 3; p++) {
            float wv = pws[(oo * 3 + p) * 97 + k];
            ull_t w2 = pk2(wv, wv);
            fma2(pa[0][p], a0, w2); fma2(pa[1][p], a1, w2);
            fma2(pa[2][p], a2, w2); fma2(pa[3][p], a3, w2);
        }
    }
    #pragma unroll
    for (int u = 0; u < 4; u++) {
        int t0 = (tt << 3) + 2 * u;
        #pragma unroll
        for (int dt = 0; dt < 2; dt++) {
            int t = t0 + dt;
            int ty = t >> 3, tx = t & 7;
            int y0 = ((wy << 3) + ty + 4) & 63;   // reverse + unshift == same map
            int x0 = ((wx << 3) + tx + 4) & 63;
            size_t row = ((size_t)((b << 12) + (y0 << 6) + x0)) * 96;
            #pragma unroll
            for (int p = 0; p < 3; p++) {
                int o = oo * 3 + p;
                float lo, hi; up2(pa[u][p], lo, hi);
                g_x2[row + o] = x[row + o] + (dt ? hi : lo) + pb[o];
            }
        }
    }
}

// =============================================================================
// K3: LayerNorm2 + fc1 + exact GELU + fc2 + residual  ->  out
// grid 4096 (64-token tiles), 256 threads. smem 173 KB (h1 never leaves smem)
// =============================================================================
__global__ void __launch_bounds__(256, 1) k3_mlp(
    const float* __restrict__ g2, const float* __restrict__ b2,
    const float* __restrict__ w1, const float* __restrict__ fb1,
    const float* __restrict__ w2, const float* __restrict__ fb2,
    float* __restrict__ out)
{
    extern __shared__ float sm[];
    float* xnt = sm;                    // [96][66]  LN2(x2), transposed
    float* h1t = sm + 6336;             // [384][66] gelu(fc1), transposed
    float* wt  = sm + 6336 + 25344;     // [384*33]  weight k-chunk

    const size_t base = (size_t)blockIdx.x * 64 * 96;
    const int tid = threadIdx.x, lane = tid & 31, warp = tid >> 5;

    {   // ---- LN2 ----
        int t = (warp << 3) + (lane >> 2), part = lane & 3;
        const float4* src = reinterpret_cast<const float4*>(
            g_x2 + base + (size_t)t * 96 + part * 24);
        float v[24]; float s = 0.f, s2 = 0.f;
        #pragma unroll
        for (int i = 0; i < 6; i++) {
            float4 f = src[i];
            v[4*i] = f.x; v[4*i+1] = f.y; v[4*i+2] = f.z; v[4*i+3] = f.w;
        }
        #pragma unroll
        for (int i = 0; i < 24; i++) { s += v[i]; s2 += v[i] * v[i]; }
        s  += __shfl_xor_sync(0xffffffffu, s, 1);  s  += __shfl_xor_sync(0xffffffffu, s, 2);
        s2 += __shfl_xor_sync(0xffffffffu, s2, 1); s2 += __shfl_xor_sync(0xffffffffu, s2, 2);
        float mu   = s * (1.f / 96.f);
        float rstd = rsqrtf(s2 * (1.f / 96.f) - mu * mu + 1e-5f);
        #pragma unroll
        for (int i = 0; i < 24; i++) {
            int c = part * 24 + i;
            xnt[c * 66 + t] = (v[i] - mu) * rstd * g2[c] + b2[c];
        }
    }

    const int tt = warp, oo = lane;

    // ---- fc1: 64x384; thread tile = 8 tokens x 12 outs (o = oo + 32p) ----
    ull_t acc[4][12];
    #pragma unroll
    for (int u = 0; u < 4; u++)
        #pragma unroll
        for (int p = 0; p < 12; p++) acc[u][p] = 0ull;

    for (int kb = 0; kb < 96; kb += 32) {
        __syncthreads();
        #pragma unroll
        for (int r = 0; r < 48; r++) {              // 384*32 / 256
            int idx = tid + r * 256;
            int o = idx >> 5, c = idx & 31;
            wt[o * 33 + c] = w1[o * 96 + kb + c];
        }
        __syncthreads();
        #pragma unroll
        for (int c = 0; c < 32; c++) {
            const ull_t* ar = reinterpret_cast<const ull_t*>(
                xnt + (kb + c) * 66 + (tt << 3));
            ull_t a0 = ar[0], a1 = ar[1], a2 = ar[2], a3 = ar[3];
            #pragma unroll
            for (int p = 0; p < 12; p++) {
                float wv = wt[(oo + 32 * p) * 33 + c];
                ull_t w2v = pk2(wv, wv);
                fma2(acc[0][p], a0, w2v); fma2(acc[1][p], a1, w2v);
                fma2(acc[2][p], a2, w2v); fma2(acc[3][p], a3, w2v);
            }
        }
    }

    #pragma unroll
    for (int p = 0; p < 12; p++) {      // bias + exact GELU -> h1t
        int o = oo + 32 * p;
        float bv = fb1[o];
        #pragma unroll
        for (int u = 0; u < 4; u++) {
            float lo, hi; up2(acc[u][p], lo, hi);
            lo += bv; hi += bv;
            lo = 0.5f * lo * (1.f + erff(lo * 0.70710678118654752f));
            hi = 0.5f * hi * (1.f + erff(hi * 0.70710678118654752f));
            int t = (tt << 3) + 2 * u;
            *reinterpret_cast<ull_t*>(h1t + o * 66 + t) = pk2(lo, hi);
        }
    }

    // ---- fc2: 64x96; thread tile = 8 tokens x 3 outs ----
    ull_t ac2[4][3];
    #pragma unroll
    for (int u = 0; u < 4; u++)
        #pragma unroll
        for (int p = 0; p < 3; p++) ac2[u][p] = 0ull;

    for (int kb = 0; kb < 384; kb += 32) {
        __syncthreads();
        #pragma unroll
        for (int r = 0; r < 12; r++) {              // 96*32 / 256
            int idx = tid + r * 256;
            int o = idx >> 5, c = idx & 31;
            wt[o * 33 + c] = w2[o * 384 + kb + c];
        }
        __syncthreads();
        #pragma unroll
        for (int c = 0; c < 32; c++) {
            const ull_t* ar = reinterpret_cast<const ull_t*>(
                h1t + (kb + c) * 66 + (tt << 3));
            ull_t a0 = ar[0], a1 = ar[1], a2 = ar[2], a3 = ar[3];
            #pragma unroll
            for (int p = 0; p < 3; p++) {
                float wv = wt[(oo + 32 * p) * 33 + c];
                ull_t w2v = pk2(wv, wv);
                fma2(ac2[0][p], a0, w2v); fma2(ac2[1][p], a1, w2v);
                fma2(ac2[2][p], a2, w2v); fma2(ac2[3][p], a3, w2v);
            }
        }
    }

    #pragma unroll
    for (int p = 0; p < 3; p++) {
        int o = oo + 32 * p;
        float bv = fb2[o];
        #pragma unroll
        for (int u = 0; u < 4; u++) {
            float lo, hi; up2(ac2[u][p], lo, hi);
            int t = (tt << 3) + 2 * u;
            out[base + (size_t)t * 96 + o]       = g_x2[base + (size_t)t * 96 + o]       + lo + bv;
            out[base + (size_t)(t + 1) * 96 + o] = g_x2[base + (size_t)(t + 1) * 96 + o] + hi + bv;
        }
    }
}

// =============================================================================
extern "C" void kernel_launch(void* const* d_in, const int* in_sizes, int n_in,
                              void* d_out, int out_size)
{
    (void)in_sizes; (void)n_in; (void)out_size;
    const float* x   = (const float*)d_in[0];
    const float* n1g = (const float*)d_in[1];
    const float* n1b = (const float*)d_in[2];
    const float* qw  = (const float*)d_in[3];
    const float* qb  = (const float*)d_in[4];
    const float* bt  = (const float*)d_in[5];
    const float* pw  = (const float*)d_in[6];
    const float* pb  = (const float*)d_in[7];
    const float* n2g = (const float*)d_in[8];
    const float* n2b = (const float*)d_in[9];
    const float* w1  = (const float*)d_in[10];
    const float* fb1 = (const float*)d_in[11];
    const float* w2  = (const float*)d_in[12];
    const float* fb2 = (const float*)d_in[13];
    float* out = (float*)d_out;

    cudaFuncSetAttribute(k1_ln_qkv,    cudaFuncAttributeMaxDynamicSharedMemorySize,  63360);
    cudaFuncSetAttribute(k2_attn_proj, cudaFuncAttributeMaxDynamicSharedMemorySize, 111744);
    cudaFuncSetAttribute(k3_mlp,       cudaFuncAttributeMaxDynamicSharedMemorySize, 177408);

    k1_ln_qkv   <<<4096, 256,  63360>>>(x, n1g, n1b, qw, qb);
    k2_attn_proj<<<4096, 256, 111744>>>(x, bt, pw, pb);
    k3_mlp      <<<4096, 256, 177408>>>(n2g, n2b, w1, fb1, w2, fb2, out);
}

// round 6
// speedup vs baseline: 1.0016x; 1.0016x over previous
#include <cuda_runtime.h>

typedef unsigned long long ull_t;

// ---------------- scratch (device globals: allocation-free rule) -------------
__device__ float g_qkv[(size_t)4096 * 64 * 288];   // [win][tok][3*C]  (302 MB)
__device__ float g_x2 [(size_t)64 * 4096 * 96];    // x + attn branch  (100 MB)

// ---------------- packed f32x2 helpers (FFMA2 path, 2x fp32 rate) ------------
static __device__ __forceinline__ ull_t pk2(float lo, float hi) {
    ull_t d;
    asm("mov.b64 %0, {%1,%2};" : "=l"(d)
        : "r"(__float_as_uint(lo)), "r"(__float_as_uint(hi)));
    return d;
}
static __device__ __forceinline__ void up2(ull_t v, float& lo, float& hi) {
    unsigned a, b;
    asm("mov.b64 {%0,%1}, %2;" : "=r"(a), "=r"(b) : "l"(v));
    lo = __uint_as_float(a); hi = __uint_as_float(b);
}
static __device__ __forceinline__ void fma2(ull_t& acc, ull_t a, ull_t b) {
    asm("fma.rn.f32x2 %0, %1, %2, %0;" : "+l"(acc) : "l"(a), "l"(b));
}

// =============================================================================
// K1: LayerNorm1 + shift(-4,-4) + window partition + QKV GEMM
// grid 4096 (one window), 256 threads. smem: xst[96][66] + ws[288][33] = 62 KB
// =============================================================================
__global__ void __launch_bounds__(256, 1) k1_ln_qkv(
    const float* __restrict__ x, const float* __restrict__ g1,
    const float* __restrict__ b1, const float* __restrict__ qw,
    const float* __restrict__ qb)
{
    extern __shared__ float sm[];
    float* xst = sm;            // [96][66]  normalized activations, transposed
    float* ws  = sm + 96 * 66;  // [288][33] weight k-chunk (padded)

    const int wnd = blockIdx.x;
    const int b = wnd >> 6, wy = (wnd >> 3) & 7, wx = wnd & 7;
    const int tid = threadIdx.x, lane = tid & 31, warp = tid >> 5;

    {   // ---- LN + gather (4 lanes per token, 24 ch each) ----
        int t = (warp << 3) + (lane >> 2);
        int part = lane & 3;
        int ty = t >> 3, tx = t & 7;
        int y0 = ((wy << 3) + ty + 4) & 63;      // roll(-4): src = (pos+4) mod 64
        int x0 = ((wx << 3) + tx + 4) & 63;
        const float4* src = reinterpret_cast<const float4*>(
            x + ((size_t)((b << 12) + (y0 << 6) + x0)) * 96 + part * 24);
        float v[24]; float s = 0.f, s2 = 0.f;
        #pragma unroll
        for (int i = 0; i < 6; i++) {
            float4 f = src[i];
            v[4*i] = f.x; v[4*i+1] = f.y; v[4*i+2] = f.z; v[4*i+3] = f.w;
        }
        #pragma unroll
        for (int i = 0; i < 24; i++) { s += v[i]; s2 += v[i] * v[i]; }
        s  += __shfl_xor_sync(0xffffffffu, s, 1);  s  += __shfl_xor_sync(0xffffffffu, s, 2);
        s2 += __shfl_xor_sync(0xffffffffu, s2, 1); s2 += __shfl_xor_sync(0xffffffffu, s2, 2);
        float mu   = s * (1.f / 96.f);
        float rstd = rsqrtf(s2 * (1.f / 96.f) - mu * mu + 1e-5f);
        #pragma unroll
        for (int i = 0; i < 24; i++) {
            int c = part * 24 + i;
            xst[c * 66 + t] = (v[i] - mu) * rstd * g1[c] + b1[c];
        }
    }

    // ---- QKV GEMM: out[64][288]; thread tile = 8 tokens (as 4 pairs) x 9 outs
    const int tt = warp, oo = lane;
    ull_t acc[4][9];
    #pragma unroll
    for (int u = 0; u < 4; u++)
        #pragma unroll
        for (int p = 0; p < 9; p++) acc[u][p] = 0ull;

    for (int kb = 0; kb < 96; kb += 32) {
        __syncthreads();
        #pragma unroll
        for (int r = 0; r < 36; r++) {              // 288*32 / 256
            int idx = tid + r * 256;
            int o = idx >> 5, c = idx & 31;
            ws[o * 33 + c] = qw[o * 96 + kb + c];
        }
        __syncthreads();
        #pragma unroll
        for (int c = 0; c < 32; c++) {
            const ull_t* ar = reinterpret_cast<const ull_t*>(
                xst + (kb + c) * 66 + (tt << 3));   // broadcast LDS.64
            ull_t a0 = ar[0], a1 = ar[1], a2 = ar[2], a3 = ar[3];
            #pragma unroll
            for (int p = 0; p < 9; p++) {
                float wv = ws[(oo * 9 + p) * 33 + c];
                ull_t w2 = pk2(wv, wv);
                fma2(acc[0][p], a0, w2); fma2(acc[1][p], a1, w2);
                fma2(acc[2][p], a2, w2); fma2(acc[3][p], a3, w2);
            }
        }
    }

    float* dst = g_qkv + (size_t)wnd * 64 * 288;
    #pragma unroll
    for (int p = 0; p < 9; p++) {
        int o = oo * 9 + p;
        float bb = qb[o];
        float sc = (o < 96) ? 0.20412414523193154f : 1.f;   // q *= 24^-0.5
        #pragma unroll
        for (int u = 0; u < 4; u++) {
            float lo, hi; up2(acc[u][p], lo, hi);
            int t0 = (tt << 3) + 2 * u;
            dst[(size_t)t0 * 288 + o]       = (lo + bb) * sc;
            dst[(size_t)(t0 + 1) * 288 + o] = (hi + bb) * sc;
        }
    }
}

// =============================================================================
// K2: windowed attention (bias + shift mask + softmax) + proj + reverse/unshift
//     + residual  ->  g_x2
// grid 4096, 256 threads (thread = (head, row)). smem 109 KB
// =============================================================================
__global__ void __launch_bounds__(256, 1) k2_attn_proj(
    const float* __restrict__ x, const float* __restrict__ btab,
    const float* __restrict__ pw, const float* __restrict__ pb)
{
    extern __shared__ float sm[];
    float* ksm = sm;                     // [4][64][24]
    float* vsm = sm + 6144;              // [4][64][24]
    float* aot = sm + 12288;             // [96][66] attn out, transposed
    float* pws = sm + 12288 + 6336;      // [96][97] proj weights (padded)

    const int wnd = blockIdx.x;
    const int b = wnd >> 6, wy = (wnd >> 3) & 7, wx = wnd & 7;
    const int tid = threadIdx.x;
    const float* qkvbase = g_qkv + (size_t)wnd * 64 * 288;
    const int h = tid >> 6, i = tid & 63;

    {   // ---- stage K, V rows ----
        const float4* sk = reinterpret_cast<const float4*>(qkvbase + i * 288 +  96 + h * 24);
        const float4* sv = reinterpret_cast<const float4*>(qkvbase + i * 288 + 192 + h * 24);
        float4* dk = reinterpret_cast<float4*>(ksm + (h * 64 + i) * 24);
        float4* dv = reinterpret_cast<float4*>(vsm + (h * 64 + i) * 24);
        #pragma unroll
        for (int u = 0; u < 6; u++) { dk[u] = sk[u]; dv[u] = sv[u]; }
    }
    for (int idx = tid; idx < 96 * 96; idx += 256) {  // stage proj_w
        int o = idx / 96, c = idx - o * 96;
        pws[o * 97 + c] = pw[idx];
    }

    ull_t q2[12];
    {   // own q row in registers (already scaled in K1)
        const float4* sq = reinterpret_cast<const float4*>(qkvbase + i * 288 + h * 24);
        #pragma unroll
        for (int u = 0; u < 6; u++) {
            float4 f = sq[u];
            q2[2*u]   = pk2(f.x, f.y);
            q2[2*u+1] = pk2(f.z, f.w);
        }
    }
    __syncthreads();

    const int iy = i >> 3, ix = i & 7;
    const int cnti = ((wy == 7) ? ((iy < 4) ? 1 : 2) : 0) * 3
                   + ((wx == 7) ? ((ix < 4) ? 1 : 2) : 0);

    float s[64];
    const float* kb_ = ksm + h * 64 * 24;
    #pragma unroll
    for (int j = 0; j < 64; j++) {
        const ull_t* kr = reinterpret_cast<const ull_t*>(kb_ + j * 24);
        ull_t a = 0ull;
        #pragma unroll
        for (int u = 0; u < 12; u++) fma2(a, q2[u], kr[u]);
        float lo, hi; up2(a, lo, hi);
        int jy = j >> 3, jx = j & 7;
        float bias = btab[((iy - jy + 7) * 15 + (ix - jx + 7)) * 4 + h];
        int cntj = ((wy == 7) ? ((jy < 4) ? 1 : 2) : 0) * 3
                 + ((wx == 7) ? ((jx < 4) ? 1 : 2) : 0);
        s[j] = lo + hi + bias + ((cnti != cntj) ? -100.f : 0.f);
    }
    float mx = -1e30f;
    #pragma unroll
    for (int j = 0; j < 64; j++) mx = fmaxf(mx, s[j]);
    float sum = 0.f;
    #pragma unroll
    for (int j = 0; j < 64; j++) { float e = __expf(s[j] - mx); s[j] = e; sum += e; }
    float inv = 1.f / sum;

    ull_t o2[12];
    #pragma unroll
    for (int u = 0; u < 12; u++) o2[u] = 0ull;
    const float* vb_ = vsm + h * 64 * 24;
    #pragma unroll
    for (int j = 0; j < 64; j++) {
        ull_t p2 = pk2(s[j], s[j]);
        const ull_t* vr = reinterpret_cast<const ull_t*>(vb_ + j * 24);
        #pragma unroll
        for (int u = 0; u < 12; u++) fma2(o2[u], p2, vr[u]);
    }
    #pragma unroll
    for (int u = 0; u < 12; u++) {
        float lo, hi; up2(o2[u], lo, hi);
        aot[(h * 24 + 2 * u)     * 66 + i] = lo * inv;
        aot[(h * 24 + 2 * u + 1) * 66 + i] = hi * inv;
    }
    __syncthreads();

    // ---- proj: out[64][96]; thread tile = 8 tokens x 3 outs ----
    const int tt = tid >> 5, oo = tid & 31;
    ull_t pa[4][3];
    #pragma unroll
    for (int u = 0; u < 4; u++)
        #pragma unroll
        for (int p = 0; p < 3; p++) pa[u][p] = 0ull;

    #pragma unroll 4
    for (int k = 0; k < 96; k++) {
        const ull_t* ar = reinterpret_cast<const ull_t*>(aot + k * 66 + (tt << 3));
        ull_t a0 = ar[0], a1 = ar[1], a2 = ar[2], a3 = ar[3];
        #pragma unroll
        for (int p = 0; p < 3; p++) {
            float wv = pws[(oo * 3 + p) * 97 + k];
            ull_t w2 = pk2(wv, wv);
            fma2(pa[0][p], a0, w2); fma2(pa[1][p], a1, w2);
            fma2(pa[2][p], a2, w2); fma2(pa[3][p], a3, w2);
        }
    }
    #pragma unroll
    for (int u = 0; u < 4; u++) {
        int t0 = (tt << 3) + 2 * u;
        #pragma unroll
        for (int dt = 0; dt < 2; dt++) {
            int t = t0 + dt;
            int ty = t >> 3, tx = t & 7;
            int y0 = ((wy << 3) + ty + 4) & 63;   // reverse + unshift == same map
            int x0 = ((wx << 3) + tx + 4) & 63;
            size_t row = ((size_t)((b << 12) + (y0 << 6) + x0)) * 96;
            #pragma unroll
            for (int p = 0; p < 3; p++) {
                int o = oo * 3 + p;
                float lo, hi; up2(pa[u][p], lo, hi);
                g_x2[row + o] = x[row + o] + (dt ? hi : lo) + pb[o];
            }
        }
    }
}

// =============================================================================
// K3: LayerNorm2 + fc1 + exact GELU + fc2 + residual  ->  out
// grid 4096 (64-token tiles), 256 threads. smem 173 KB (h1 never leaves smem)
// =============================================================================
__global__ void __launch_bounds__(256, 1) k3_mlp(
    const float* __restrict__ g2, const float* __restrict__ b2,
    const float* __restrict__ w1, const float* __restrict__ fb1,
    const float* __restrict__ w2, const float* __restrict__ fb2,
    float* __restrict__ out)
{
    extern __shared__ float sm[];
    float* xnt = sm;                    // [96][66]  LN2(x2), transposed
    float* h1t = sm + 6336;             // [384][66] gelu(fc1), transposed
    float* wt  = sm + 6336 + 25344;     // [384*33]  weight k-chunk

    const size_t base = (size_t)blockIdx.x * 64 * 96;
    const int tid = threadIdx.x, lane = tid & 31, warp = tid >> 5;

    {   // ---- LN2 ----
        int t = (warp << 3) + (lane >> 2), part = lane & 3;
        const float4* src = reinterpret_cast<const float4*>(
            g_x2 + base + (size_t)t * 96 + part * 24);
        float v[24]; float s = 0.f, s2 = 0.f;
        #pragma unroll
        for (int i = 0; i < 6; i++) {
            float4 f = src[i];
            v[4*i] = f.x; v[4*i+1] = f.y; v[4*i+2] = f.z; v[4*i+3] = f.w;
        }
        #pragma unroll
        for (int i = 0; i < 24; i++) { s += v[i]; s2 += v[i] * v[i]; }
        s  += __shfl_xor_sync(0xffffffffu, s, 1);  s  += __shfl_xor_sync(0xffffffffu, s, 2);
        s2 += __shfl_xor_sync(0xffffffffu, s2, 1); s2 += __shfl_xor_sync(0xffffffffu, s2, 2);
        float mu   = s * (1.f / 96.f);
        float rstd = rsqrtf(s2 * (1.f / 96.f) - mu * mu + 1e-5f);
        #pragma unroll
        for (int i = 0; i < 24; i++) {
            int c = part * 24 + i;
            xnt[c * 66 + t] = (v[i] - mu) * rstd * g2[c] + b2[c];
        }
    }

    const int tt = warp, oo = lane;

    // ---- fc1: 64x384; thread tile = 8 tokens x 12 outs (o = oo + 32p) ----
    ull_t acc[4][12];
    #pragma unroll
    for (int u = 0; u < 4; u++)
        #pragma unroll
        for (int p = 0; p < 12; p++) acc[u][p] = 0ull;

    for (int kb = 0; kb < 96; kb += 32) {
        __syncthreads();
        #pragma unroll
        for (int r = 0; r < 48; r++) {              // 384*32 / 256
            int idx = tid + r * 256;
            int o = idx >> 5, c = idx & 31;
            wt[o * 33 + c] = w1[o * 96 + kb + c];
        }
        __syncthreads();
        #pragma unroll
        for (int c = 0; c < 32; c++) {
            const ull_t* ar = reinterpret_cast<const ull_t*>(
                xnt + (kb + c) * 66 + (tt << 3));
            ull_t a0 = ar[0], a1 = ar[1], a2 = ar[2], a3 = ar[3];
            #pragma unroll
            for (int p = 0; p < 12; p++) {
                float wv = wt[(oo + 32 * p) * 33 + c];
                ull_t w2v = pk2(wv, wv);
                fma2(acc[0][p], a0, w2v); fma2(acc[1][p], a1, w2v);
                fma2(acc[2][p], a2, w2v); fma2(acc[3][p], a3, w2v);
            }
        }
    }

    #pragma unroll
    for (int p = 0; p < 12; p++) {      // bias + exact GELU -> h1t
        int o = oo + 32 * p;
        float bv = fb1[o];
        #pragma unroll
        for (int u = 0; u < 4; u++) {
            float lo, hi; up2(acc[u][p], lo, hi);
            lo += bv; hi += bv;
            lo = 0.5f * lo * (1.f + erff(lo * 0.70710678118654752f));
            hi = 0.5f * hi * (1.f + erff(hi * 0.70710678118654752f));
            int t = (tt << 3) + 2 * u;
            *reinterpret_cast<ull_t*>(h1t + o * 66 + t) = pk2(lo, hi);
        }
    }

    // ---- fc2: 64x96; thread tile = 8 tokens x 3 outs ----
    ull_t ac2[4][3];
    #pragma unroll
    for (int u = 0; u < 4; u++)
        #pragma unroll
        for (int p = 0; p < 3; p++) ac2[u][p] = 0ull;

    for (int kb = 0; kb < 384; kb += 32) {
        __syncthreads();
        #pragma unroll
        for (int r = 0; r < 12; r++) {              // 96*32 / 256
            int idx = tid + r * 256;
            int o = idx >> 5, c = idx & 31;
            wt[o * 33 + c] = w2[o * 384 + kb + c];
        }
        __syncthreads();
        #pragma unroll
        for (int c = 0; c < 32; c++) {
            const ull_t* ar = reinterpret_cast<const ull_t*>(
                h1t + (kb + c) * 66 + (tt << 3));
            ull_t a0 = ar[0], a1 = ar[1], a2 = ar[2], a3 = ar[3];
            #pragma unroll
            for (int p = 0; p < 3; p++) {
                float wv = wt[(oo + 32 * p) * 33 + c];
                ull_t w2v = pk2(wv, wv);
                fma2(ac2[0][p], a0, w2v); fma2(ac2[1][p], a1, w2v);
                fma2(ac2[2][p], a2, w2v); fma2(ac2[3][p], a3, w2v);
            }
        }
    }

    #pragma unroll
    for (int p = 0; p < 3; p++) {
        int o = oo + 32 * p;
        float bv = fb2[o];
        #pragma unroll
        for (int u = 0; u < 4; u++) {
            float lo, hi; up2(ac2[u][p], lo, hi);
            int t = (tt << 3) + 2 * u;
            out[base + (size_t)t * 96 + o]       = g_x2[base + (size_t)t * 96 + o]       + lo + bv;
            out[base + (size_t)(t + 1) * 96 + o] = g_x2[base + (size_t)(t + 1) * 96 + o] + hi + bv;
        }
    }
}

// =============================================================================
extern "C" void kernel_launch(void* const* d_in, const int* in_sizes, int n_in,
                              void* d_out, int out_size)
{
    (void)in_sizes; (void)n_in; (void)out_size;
    const float* x   = (const float*)d_in[0];
    const float* n1g = (const float*)d_in[1];
    const float* n1b = (const float*)d_in[2];
    const float* qw  = (const float*)d_in[3];
    const float* qb  = (const float*)d_in[4];
    const float* bt  = (const float*)d_in[5];
    const float* pw  = (const float*)d_in[6];
    const float* pb  = (const float*)d_in[7];
    const float* n2g = (const float*)d_in[8];
    const float* n2b = (const float*)d_in[9];
    const float* w1  = (const float*)d_in[10];
    const float* fb1 = (const float*)d_in[11];
    const float* w2  = (const float*)d_in[12];
    const float* fb2 = (const float*)d_in[13];
    float* out = (float*)d_out;

    cudaFuncSetAttribute(k1_ln_qkv,    cudaFuncAttributeMaxDynamicSharedMemorySize,  63360);
    cudaFuncSetAttribute(k2_attn_proj, cudaFuncAttributeMaxDynamicSharedMemorySize, 111744);
    cudaFuncSetAttribute(k3_mlp,       cudaFuncAttributeMaxDynamicSharedMemorySize, 177408);

    k1_ln_qkv   <<<4096, 256,  63360>>>(x, n1g, n1b, qw, qb);
    k2_attn_proj<<<4096, 256, 111744>>>(x, bt, pw, pb);
    k3_mlp      <<<4096, 256, 177408>>>(n2g, n2b, w1, fb1, w2, fb2, out);
}